// round 3
// baseline (speedup 1.0000x reference)
#include <cuda_runtime.h>

// Problem constants (fixed by the reference)
#define H_DIM 1024
#define N_EXP 8
#define N_TOK 8192      // B*S = 4*2048
#define TOPK  2

// GEMM tile
#define BM 64
#define BN 64
#define BK 32
#define NTHREADS 256

// -------- scratch (allocation-free: __device__ globals) --------
__device__ int   d_counts[N_EXP];
__device__ int   d_tok [N_EXP][N_TOK];
__device__ float d_gate[N_EXP][N_TOK];

// ---------------- kernel 1: zero out + counters ----------------
__global__ void moe_zero_kernel(float4* __restrict__ out4) {
    if (blockIdx.x == 0 && threadIdx.x < N_EXP) d_counts[threadIdx.x] = 0;
    size_t idx = (size_t)blockIdx.x * blockDim.x + threadIdx.x;
    // N_TOK*H_DIM/4 float4 elements = 2,097,152
    if (idx < (size_t)N_TOK * H_DIM / 4)
        out4[idx] = make_float4(0.f, 0.f, 0.f, 0.f);
}

// ---------------- kernel 2: gate + top-2 assignment -------------
// one warp per token
__global__ void moe_gate_kernel(const float* __restrict__ x,
                                const float* __restrict__ gw,
                                const float* __restrict__ gb) {
    int gwarp = (blockIdx.x * blockDim.x + threadIdx.x) >> 5;
    int lane  = threadIdx.x & 31;
    if (gwarp >= N_TOK) return;

    const float* xr = x + (size_t)gwarp * H_DIM;
    float acc[N_EXP];
#pragma unroll
    for (int e = 0; e < N_EXP; e++) acc[e] = 0.f;

    for (int h = lane; h < H_DIM; h += 32) {
        float xv = xr[h];
#pragma unroll
        for (int e = 0; e < N_EXP; e++)
            acc[e] += xv * gw[e * H_DIM + h];
    }
#pragma unroll
    for (int e = 0; e < N_EXP; e++) {
#pragma unroll
        for (int off = 16; off; off >>= 1)
            acc[e] += __shfl_xor_sync(0xffffffffu, acc[e], off);
    }

    if (lane == 0) {
        float logit[N_EXP];
        float mx = -1e30f;
#pragma unroll
        for (int e = 0; e < N_EXP; e++) {
            logit[e] = acc[e] + gb[e];
            mx = fmaxf(mx, logit[e]);
        }
        float p[N_EXP];
        float s = 0.f;
#pragma unroll
        for (int e = 0; e < N_EXP; e++) { p[e] = __expf(logit[e] - mx); s += p[e]; }
        float inv = 1.f / s;
#pragma unroll
        for (int e = 0; e < N_EXP; e++) p[e] *= inv;

        // top-2 (strict > keeps lowest index on ties, matching jax top_k)
        int i0 = 0;
#pragma unroll
        for (int e = 1; e < N_EXP; e++) if (p[e] > p[i0]) i0 = e;
        int i1 = (i0 == 0) ? 1 : 0;
#pragma unroll
        for (int e = 0; e < N_EXP; e++)
            if (e != i0 && p[e] > p[i1]) i1 = e;

        int pos0 = atomicAdd(&d_counts[i0], 1);
        d_tok [i0][pos0] = gwarp;
        d_gate[i0][pos0] = p[i0];
        int pos1 = atomicAdd(&d_counts[i1], 1);
        d_tok [i1][pos1] = gwarp;
        d_gate[i1][pos1] = p[i1];
    }
}

// ---------------- kernel 3: grouped GEMM + scatter ---------------
// grid: (BN tiles = 16, max BM tiles = 128, experts = 8), 256 threads
__global__ __launch_bounds__(NTHREADS)
void moe_gemm_kernel(const float* __restrict__ x,
                     const float* __restrict__ w,   // [E][H][H] (out, in)
                     const float* __restrict__ bexp,// [E][H]
                     float* __restrict__ out) {
    int e   = blockIdx.z;
    int cnt = d_counts[e];
    int m0  = blockIdx.y * BM;
    if (m0 >= cnt) return;
    int n0  = blockIdx.x * BN;

    __shared__ float Xs[BK][BM + 1];
    __shared__ float Ws[BK][BN + 1];
    __shared__ int   tok_s[BM];
    __shared__ float gw_s [BM];

    int tid = threadIdx.x;
    if (tid < BM) {
        int m = m0 + tid;
        if (m < cnt) {
            tok_s[tid] = d_tok [e][m];
            gw_s [tid] = d_gate[e][m];
        } else {
            tok_s[tid] = -1;
            gw_s [tid] = 0.f;
        }
    }
    __syncthreads();

    const float* wbase = w + (size_t)e * H_DIM * H_DIM;
    int tx = tid & 15;   // n group
    int ty = tid >> 4;   // m group
    float acc[4][4];
#pragma unroll
    for (int i = 0; i < 4; i++)
#pragma unroll
        for (int j = 0; j < 4; j++) acc[i][j] = 0.f;

    for (int k0 = 0; k0 < H_DIM; k0 += BK) {
        // load X tile: gather rows by token id (coalesced along k)
#pragma unroll
        for (int it = 0; it < (BK * BM) / NTHREADS; it++) {
            int idx = tid + it * NTHREADS;
            int kk = idx & (BK - 1);
            int mm = idx >> 5;           // / BK
            int t  = tok_s[mm];
            Xs[kk][mm] = (t >= 0) ? x[(size_t)t * H_DIM + k0 + kk] : 0.f;
        }
        // load W tile (coalesced along k)
#pragma unroll
        for (int it = 0; it < (BK * BN) / NTHREADS; it++) {
            int idx = tid + it * NTHREADS;
            int kk = idx & (BK - 1);
            int nn = idx >> 5;
            Ws[kk][nn] = wbase[(size_t)(n0 + nn) * H_DIM + k0 + kk];
        }
        __syncthreads();

#pragma unroll
        for (int kk = 0; kk < BK; kk++) {
            float a0 = Xs[kk][ty * 4 + 0];
            float a1 = Xs[kk][ty * 4 + 1];
            float a2 = Xs[kk][ty * 4 + 2];
            float a3 = Xs[kk][ty * 4 + 3];
            float b0 = Ws[kk][tx * 4 + 0];
            float b1 = Ws[kk][tx * 4 + 1];
            float b2 = Ws[kk][tx * 4 + 2];
            float b3 = Ws[kk][tx * 4 + 3];
            acc[0][0] += a0 * b0; acc[0][1] += a0 * b1; acc[0][2] += a0 * b2; acc[0][3] += a0 * b3;
            acc[1][0] += a1 * b0; acc[1][1] += a1 * b1; acc[1][2] += a1 * b2; acc[1][3] += a1 * b3;
            acc[2][0] += a2 * b0; acc[2][1] += a2 * b1; acc[2][2] += a2 * b2; acc[2][3] += a2 * b3;
            acc[3][0] += a3 * b0; acc[3][1] += a3 * b1; acc[3][2] += a3 * b2; acc[3][3] += a3 * b3;
        }
        __syncthreads();
    }

    // epilogue: y = gate * (acc + bias), scatter-accumulate per token row
#pragma unroll
    for (int i = 0; i < 4; i++) {
        int m = ty * 4 + i;
        int t = tok_s[m];
        if (t < 0) continue;
        float g = gw_s[m];
#pragma unroll
        for (int j = 0; j < 4; j++) {
            int n = n0 + tx * 4 + j;
            float v = g * (acc[i][j] + bexp[e * H_DIM + n]);
            atomicAdd(&out[(size_t)t * H_DIM + n], v);
        }
    }
}

// ------------------------- launcher ------------------------------
extern "C" void kernel_launch(void* const* d_in, const int* in_sizes, int n_in,
                              void* d_out, int out_size) {
    const float* x   = (const float*)d_in[0];  // [4,2048,1024]
    const float* gw  = (const float*)d_in[1];  // [8,1024]
    const float* gb  = (const float*)d_in[2];  // [8]
    const float* ew  = (const float*)d_in[3];  // [8,1024,1024]
    const float* eb  = (const float*)d_in[4];  // [8,1024]
    float* out = (float*)d_out;

    // 1) zero output + counters
    {
        int n4 = N_TOK * H_DIM / 4;
        moe_zero_kernel<<<(n4 + 255) / 256, 256>>>((float4*)out);
    }
    // 2) gate + assignment (one warp/token)
    {
        int warps_per_block = 8;
        int blocks = N_TOK / warps_per_block;
        moe_gate_kernel<<<blocks, warps_per_block * 32>>>(x, gw, gb);
    }
    // 3) grouped GEMM
    {
        dim3 grid(H_DIM / BN, N_TOK / BM, N_EXP);  // (16, 128, 8)
        moe_gemm_kernel<<<grid, NTHREADS>>>(x, ew, eb, out);
    }
}

// round 4
// speedup vs baseline: 2.0929x; 2.0929x over previous
#include <cuda_runtime.h>

// Problem constants (fixed by the reference)
#define H_DIM 1024
#define N_EXP 8
#define N_TOK 8192      // B*S = 4*2048
#define TOPK  2

// GEMM tile
#define BM 128
#define BN 128
#define BK 16
#define NTHREADS 256
#define NK (H_DIM / BK)   // 64

// -------- scratch (allocation-free: __device__ globals) --------
__device__ int   d_counts[N_EXP];
__device__ int   d_tok [N_EXP][N_TOK];
__device__ float d_gate[N_EXP][N_TOK];

// ---------------- packed f32x2 helpers --------------------------
__device__ __forceinline__ unsigned long long pack2(float x, float y) {
    unsigned long long r;
    asm("mov.b64 %0, {%1, %2};" : "=l"(r) : "f"(x), "f"(y));
    return r;
}
__device__ __forceinline__ void unpack2(unsigned long long v, float& x, float& y) {
    asm("mov.b64 {%0, %1}, %2;" : "=f"(x), "=f"(y) : "l"(v));
}
__device__ __forceinline__ void fma2(unsigned long long& d,
                                     unsigned long long a,
                                     unsigned long long b) {
    asm("fma.rn.f32x2 %0, %1, %2, %3;" : "=l"(d) : "l"(a), "l"(b), "l"(d));
}

// ---------------- kernel 1: zero out + counters ----------------
__global__ void moe_zero_kernel(float4* __restrict__ out4) {
    if (blockIdx.x == 0 && threadIdx.x < N_EXP) d_counts[threadIdx.x] = 0;
    size_t idx = (size_t)blockIdx.x * blockDim.x + threadIdx.x;
    if (idx < (size_t)N_TOK * H_DIM / 4)
        out4[idx] = make_float4(0.f, 0.f, 0.f, 0.f);
}

// ---------------- kernel 2: gate + top-2 assignment -------------
// one warp per token
__global__ void moe_gate_kernel(const float* __restrict__ x,
                                const float* __restrict__ gw,
                                const float* __restrict__ gb) {
    int gwarp = (blockIdx.x * blockDim.x + threadIdx.x) >> 5;
    int lane  = threadIdx.x & 31;
    if (gwarp >= N_TOK) return;

    const float* xr = x + (size_t)gwarp * H_DIM;
    float acc[N_EXP];
#pragma unroll
    for (int e = 0; e < N_EXP; e++) acc[e] = 0.f;

    for (int h = lane; h < H_DIM; h += 32) {
        float xv = xr[h];
#pragma unroll
        for (int e = 0; e < N_EXP; e++)
            acc[e] += xv * gw[e * H_DIM + h];
    }
#pragma unroll
    for (int e = 0; e < N_EXP; e++) {
#pragma unroll
        for (int off = 16; off; off >>= 1)
            acc[e] += __shfl_xor_sync(0xffffffffu, acc[e], off);
    }

    if (lane == 0) {
        float logit[N_EXP];
        float mx = -1e30f;
#pragma unroll
        for (int e = 0; e < N_EXP; e++) {
            logit[e] = acc[e] + gb[e];
            mx = fmaxf(mx, logit[e]);
        }
        float p[N_EXP];
        float s = 0.f;
#pragma unroll
        for (int e = 0; e < N_EXP; e++) { p[e] = __expf(logit[e] - mx); s += p[e]; }
        float inv = 1.f / s;
#pragma unroll
        for (int e = 0; e < N_EXP; e++) p[e] *= inv;

        // top-2 (strict > keeps lowest index on ties, matching jax top_k)
        int i0 = 0;
#pragma unroll
        for (int e = 1; e < N_EXP; e++) if (p[e] > p[i0]) i0 = e;
        int i1 = (i0 == 0) ? 1 : 0;
#pragma unroll
        for (int e = 0; e < N_EXP; e++)
            if (e != i0 && p[e] > p[i1]) i1 = e;

        int pos0 = atomicAdd(&d_counts[i0], 1);
        d_tok [i0][pos0] = gwarp;
        d_gate[i0][pos0] = p[i0];
        int pos1 = atomicAdd(&d_counts[i1], 1);
        d_tok [i1][pos1] = gwarp;
        d_gate[i1][pos1] = p[i1];
    }
}

// ---------------- kernel 3: grouped GEMM + scatter ---------------
// grid: (H/BN = 8, max token tiles = 64, experts = 8), 256 threads
// 128x128x16 tile, 8x8 per thread via packed f32x2 FMAs, double-buffered smem.
__global__ __launch_bounds__(NTHREADS, 2)
void moe_gemm_kernel(const float* __restrict__ x,
                     const float* __restrict__ w,   // [E][H][H] (out, in)
                     const float* __restrict__ bexp,// [E][H]
                     float* __restrict__ out) {
    const int e   = blockIdx.z;
    const int cnt = d_counts[e];
    const int m0  = blockIdx.y * BM;
    if (m0 >= cnt) return;
    const int n0  = blockIdx.x * BN;

    __shared__ float Xs[2][BK][BM + 4];
    __shared__ float Ws[2][BK][BN + 4];
    __shared__ int   tok_s[BM];
    __shared__ float gw_s [BM];

    const int tid = threadIdx.x;
    if (tid < BM) {
        int m = m0 + tid;
        if (m < cnt) {
            tok_s[tid] = d_tok [e][m];
            gw_s [tid] = d_gate[e][m];
        } else {
            tok_s[tid] = -1;
            gw_s [tid] = 0.f;
        }
    }
    __syncthreads();

    const float* wbase = w + (size_t)e * H_DIM * H_DIM;
    const int tx = tid & 15;   // n group
    const int ty = tid >> 4;   // m group

    // per-thread load coordinates (fixed across k-tiles)
    // idx = tid + it*256 ; kk4 = idx&3 (which float4 along k) ; mm = idx>>2 (row)
    const int kk4_0 = tid & 3;
    const int row_0 = tid >> 2;          // 0..63
    const int row_1 = (tid + 256) >> 2;  // 64..127

    const int t0 = tok_s[row_0];
    const int t1 = tok_s[row_1];
    const float* xrow0 = (t0 >= 0) ? x + (size_t)t0 * H_DIM + kk4_0 * 4 : nullptr;
    const float* xrow1 = (t1 >= 0) ? x + (size_t)t1 * H_DIM + kk4_0 * 4 : nullptr;
    const float* wrow0 = wbase + (size_t)(n0 + row_0) * H_DIM + kk4_0 * 4;
    const float* wrow1 = wbase + (size_t)(n0 + row_1) * H_DIM + kk4_0 * 4;

    const float4 zero4 = make_float4(0.f, 0.f, 0.f, 0.f);
    float4 xr0, xr1, wr0, wr1;

    // accumulators: 8 m-rows x 4 packed n-pairs (= 8 n-cols)
    unsigned long long acc2[8][4];
#pragma unroll
    for (int i = 0; i < 8; i++)
#pragma unroll
        for (int j = 0; j < 4; j++) acc2[i][j] = 0ull;

    // ---- prologue: load k-tile 0, store buf 0 ----
    {
        xr0 = xrow0 ? *(const float4*)(xrow0) : zero4;
        xr1 = xrow1 ? *(const float4*)(xrow1) : zero4;
        wr0 = *(const float4*)(wrow0);
        wr1 = *(const float4*)(wrow1);
        Xs[0][kk4_0 * 4 + 0][row_0] = xr0.x;
        Xs[0][kk4_0 * 4 + 1][row_0] = xr0.y;
        Xs[0][kk4_0 * 4 + 2][row_0] = xr0.z;
        Xs[0][kk4_0 * 4 + 3][row_0] = xr0.w;
        Xs[0][kk4_0 * 4 + 0][row_1] = xr1.x;
        Xs[0][kk4_0 * 4 + 1][row_1] = xr1.y;
        Xs[0][kk4_0 * 4 + 2][row_1] = xr1.z;
        Xs[0][kk4_0 * 4 + 3][row_1] = xr1.w;
        Ws[0][kk4_0 * 4 + 0][row_0] = wr0.x;
        Ws[0][kk4_0 * 4 + 1][row_0] = wr0.y;
        Ws[0][kk4_0 * 4 + 2][row_0] = wr0.z;
        Ws[0][kk4_0 * 4 + 3][row_0] = wr0.w;
        Ws[0][kk4_0 * 4 + 0][row_1] = wr1.x;
        Ws[0][kk4_0 * 4 + 1][row_1] = wr1.y;
        Ws[0][kk4_0 * 4 + 2][row_1] = wr1.z;
        Ws[0][kk4_0 * 4 + 3][row_1] = wr1.w;
    }
    __syncthreads();

    for (int kt = 0; kt < NK; kt++) {
        const int cur = kt & 1;
        const int koff = (kt + 1) * BK;

        // prefetch next k-tile into registers (hidden under compute)
        if (kt + 1 < NK) {
            xr0 = xrow0 ? *(const float4*)(xrow0 + koff) : zero4;
            xr1 = xrow1 ? *(const float4*)(xrow1 + koff) : zero4;
            wr0 = *(const float4*)(wrow0 + koff);
            wr1 = *(const float4*)(wrow1 + koff);
        }

        // compute on buffer `cur`
#pragma unroll
        for (int kk = 0; kk < BK; kk++) {
            float a[8];
            *(float4*)&a[0] = *(const float4*)&Xs[cur][kk][ty * 4];
            *(float4*)&a[4] = *(const float4*)&Xs[cur][kk][64 + ty * 4];
            const ulonglong2 bl = *(const ulonglong2*)&Ws[cur][kk][tx * 4];
            const ulonglong2 bh = *(const ulonglong2*)&Ws[cur][kk][64 + tx * 4];
            unsigned long long b2[4];
            b2[0] = bl.x; b2[1] = bl.y; b2[2] = bh.x; b2[3] = bh.y;
#pragma unroll
            for (int i = 0; i < 8; i++) {
                const unsigned long long a2 = pack2(a[i], a[i]);
#pragma unroll
                for (int j = 0; j < 4; j++)
                    fma2(acc2[i][j], a2, b2[j]);
            }
        }

        if (kt + 1 < NK) {
            const int nxt = cur ^ 1;
            Xs[nxt][kk4_0 * 4 + 0][row_0] = xr0.x;
            Xs[nxt][kk4_0 * 4 + 1][row_0] = xr0.y;
            Xs[nxt][kk4_0 * 4 + 2][row_0] = xr0.z;
            Xs[nxt][kk4_0 * 4 + 3][row_0] = xr0.w;
            Xs[nxt][kk4_0 * 4 + 0][row_1] = xr1.x;
            Xs[nxt][kk4_0 * 4 + 1][row_1] = xr1.y;
            Xs[nxt][kk4_0 * 4 + 2][row_1] = xr1.z;
            Xs[nxt][kk4_0 * 4 + 3][row_1] = xr1.w;
            Ws[nxt][kk4_0 * 4 + 0][row_0] = wr0.x;
            Ws[nxt][kk4_0 * 4 + 1][row_0] = wr0.y;
            Ws[nxt][kk4_0 * 4 + 2][row_0] = wr0.z;
            Ws[nxt][kk4_0 * 4 + 3][row_0] = wr0.w;
            Ws[nxt][kk4_0 * 4 + 0][row_1] = wr1.x;
            Ws[nxt][kk4_0 * 4 + 1][row_1] = wr1.y;
            Ws[nxt][kk4_0 * 4 + 2][row_1] = wr1.z;
            Ws[nxt][kk4_0 * 4 + 3][row_1] = wr1.w;
            __syncthreads();
        }
    }

    // epilogue: y = gate * (acc + bias), scatter-accumulate per token row
#pragma unroll
    for (int i = 0; i < 8; i++) {
        const int mm = ((i >> 2) * 64) + ty * 4 + (i & 3);
        const int t = tok_s[mm];
        if (t < 0) continue;
        const float g = gw_s[mm];
        float* orow = out + (size_t)t * H_DIM + n0;
        const float* brow = bexp + e * H_DIM + n0;
#pragma unroll
        for (int j = 0; j < 4; j++) {
            const int nn = ((j >> 1) * 64) + tx * 4 + ((j & 1) * 2);
            float v0, v1;
            unpack2(acc2[i][j], v0, v1);
            atomicAdd(&orow[nn + 0], g * (v0 + brow[nn + 0]));
            atomicAdd(&orow[nn + 1], g * (v1 + brow[nn + 1]));
        }
    }
}

// ------------------------- launcher ------------------------------
extern "C" void kernel_launch(void* const* d_in, const int* in_sizes, int n_in,
                              void* d_out, int out_size) {
    const float* x   = (const float*)d_in[0];  // [4,2048,1024]
    const float* gw  = (const float*)d_in[1];  // [8,1024]
    const float* gb  = (const float*)d_in[2];  // [8]
    const float* ew  = (const float*)d_in[3];  // [8,1024,1024]
    const float* eb  = (const float*)d_in[4];  // [8,1024]
    float* out = (float*)d_out;

    // 1) zero output + counters
    {
        int n4 = N_TOK * H_DIM / 4;
        moe_zero_kernel<<<(n4 + 255) / 256, 256>>>((float4*)out);
    }
    // 2) gate + assignment (one warp/token)
    {
        int warps_per_block = 8;
        int blocks = N_TOK / warps_per_block;
        moe_gate_kernel<<<blocks, warps_per_block * 32>>>(x, gw, gb);
    }
    // 3) grouped GEMM (128x128 tiles, f32x2 packed FMA)
    {
        dim3 grid(H_DIM / BN, N_TOK / BM, N_EXP);  // (8, 64, 8)
        moe_gemm_kernel<<<grid, NTHREADS>>>(x, ew, eb, out);
    }
}

// round 6
// speedup vs baseline: 4.5648x; 2.1811x over previous
#include <cuda_runtime.h>
#include <cuda_bf16.h>
#include <cstdint>

// Problem constants
#define H_DIM 1024
#define N_EXP 8
#define N_TOK 8192      // B*S
#define BM 128
#define BN 128
#define KT 64                 // k-elements per smem tile (bf16): 128B rows
#define NKT (H_DIM / KT)      // 16
#define NTHREADS 256

// SMEM layout (dynamic)
#define SM_TOK    0                       // 128 ints
#define SM_GATE   512                     // 128 floats
#define SM_TILES  1024
#define TILE_BYTES 16384                  // 128 rows x 128B
#define BUF_BYTES (4 * TILE_BYTES)        // Ah, Al, Bh, Bl
#define SMEM_TOTAL (SM_TILES + 2 * BUF_BYTES)   // 132096

// -------- scratch (allocation-free: __device__ globals) --------
__device__ int   d_counts[N_EXP];
__device__ int   d_tok [N_EXP][N_TOK];
__device__ float d_gate[N_EXP][N_TOK];
__device__ __nv_bfloat16 d_xh[(size_t)N_TOK * H_DIM];
__device__ __nv_bfloat16 d_xl[(size_t)N_TOK * H_DIM];
__device__ __nv_bfloat16 d_wh[(size_t)N_EXP * H_DIM * H_DIM];
__device__ __nv_bfloat16 d_wl[(size_t)N_EXP * H_DIM * H_DIM];

// ---------------- PTX helpers (baseline sm_80+ features only) ----
__device__ __forceinline__ uint32_t smem_to_u32(const void* p) {
    uint32_t a;
    asm("{ .reg .u64 t; cvta.to.shared.u64 t, %1; cvt.u32.u64 %0, t; }"
        : "=r"(a) : "l"(p));
    return a;
}
__device__ __forceinline__ void cp_async16(uint32_t dst, const void* src, uint32_t src_size) {
    asm volatile("cp.async.cg.shared.global [%0], [%1], 16, %2;"
                 :: "r"(dst), "l"(src), "r"(src_size) : "memory");
}
__device__ __forceinline__ void cp_commit() {
    asm volatile("cp.async.commit_group;" ::: "memory");
}
__device__ __forceinline__ void cp_wait1() {
    asm volatile("cp.async.wait_group 1;" ::: "memory");
}
__device__ __forceinline__ void cp_wait0() {
    asm volatile("cp.async.wait_group 0;" ::: "memory");
}
__device__ __forceinline__ void ldsm_x4(uint32_t* r, uint32_t addr) {
    asm volatile("ldmatrix.sync.aligned.m8n8.x4.shared.b16 {%0,%1,%2,%3}, [%4];"
                 : "=r"(r[0]), "=r"(r[1]), "=r"(r[2]), "=r"(r[3]) : "r"(addr));
}
__device__ __forceinline__ void mma_bf16(float* d, const uint32_t* a, const uint32_t* b) {
    asm volatile("mma.sync.aligned.m16n8k16.row.col.f32.bf16.bf16.f32 "
                 "{%0,%1,%2,%3}, {%4,%5,%6,%7}, {%8,%9}, {%0,%1,%2,%3};"
                 : "+f"(d[0]), "+f"(d[1]), "+f"(d[2]), "+f"(d[3])
                 : "r"(a[0]), "r"(a[1]), "r"(a[2]), "r"(a[3]),
                   "r"(b[0]), "r"(b[1]));
}

// ---------------- kernel 1: zero out + counters ----------------
__global__ void moe_zero_kernel(float4* __restrict__ out4) {
    if (blockIdx.x == 0 && threadIdx.x < N_EXP) d_counts[threadIdx.x] = 0;
    size_t idx = (size_t)blockIdx.x * blockDim.x + threadIdx.x;
    if (idx < (size_t)N_TOK * H_DIM / 4)
        out4[idx] = make_float4(0.f, 0.f, 0.f, 0.f);
}

// ---------------- kernel 2: hi/lo bf16 split --------------------
__global__ void moe_convert_kernel(const float4* __restrict__ src, int mode, int n4) {
    int i = blockIdx.x * blockDim.x + threadIdx.x;
    if (i >= n4) return;
    float4 v = src[i];
    __nv_bfloat16 h0 = __float2bfloat16(v.x);
    __nv_bfloat16 h1 = __float2bfloat16(v.y);
    __nv_bfloat16 h2 = __float2bfloat16(v.z);
    __nv_bfloat16 h3 = __float2bfloat16(v.w);
    __nv_bfloat16 l0 = __float2bfloat16(v.x - __bfloat162float(h0));
    __nv_bfloat16 l1 = __float2bfloat16(v.y - __bfloat162float(h1));
    __nv_bfloat16 l2 = __float2bfloat16(v.z - __bfloat162float(h2));
    __nv_bfloat16 l3 = __float2bfloat16(v.w - __bfloat162float(h3));
    __nv_bfloat162* hi = (__nv_bfloat162*)(mode ? d_wh : d_xh);
    __nv_bfloat162* lo = (__nv_bfloat162*)(mode ? d_wl : d_xl);
    hi[i * 2 + 0] = __halves2bfloat162(h0, h1);
    hi[i * 2 + 1] = __halves2bfloat162(h2, h3);
    lo[i * 2 + 0] = __halves2bfloat162(l0, l1);
    lo[i * 2 + 1] = __halves2bfloat162(l2, l3);
}

// ---------------- kernel 3: gate + top-2 assignment -------------
__global__ void moe_gate_kernel(const float* __restrict__ x,
                                const float* __restrict__ gw,
                                const float* __restrict__ gb) {
    int gwarp = (blockIdx.x * blockDim.x + threadIdx.x) >> 5;
    int lane  = threadIdx.x & 31;
    if (gwarp >= N_TOK) return;

    const float* xr = x + (size_t)gwarp * H_DIM;
    float acc[N_EXP];
#pragma unroll
    for (int e = 0; e < N_EXP; e++) acc[e] = 0.f;
    for (int h = lane; h < H_DIM; h += 32) {
        float xv = xr[h];
#pragma unroll
        for (int e = 0; e < N_EXP; e++) acc[e] += xv * gw[e * H_DIM + h];
    }
#pragma unroll
    for (int e = 0; e < N_EXP; e++) {
#pragma unroll
        for (int off = 16; off; off >>= 1)
            acc[e] += __shfl_xor_sync(0xffffffffu, acc[e], off);
    }
    if (lane == 0) {
        float logit[N_EXP], mx = -1e30f;
#pragma unroll
        for (int e = 0; e < N_EXP; e++) { logit[e] = acc[e] + gb[e]; mx = fmaxf(mx, logit[e]); }
        float p[N_EXP], s = 0.f;
#pragma unroll
        for (int e = 0; e < N_EXP; e++) { p[e] = __expf(logit[e] - mx); s += p[e]; }
        float inv = 1.f / s;
#pragma unroll
        for (int e = 0; e < N_EXP; e++) p[e] *= inv;
        int i0 = 0;
#pragma unroll
        for (int e = 1; e < N_EXP; e++) if (p[e] > p[i0]) i0 = e;
        int i1 = (i0 == 0) ? 1 : 0;
#pragma unroll
        for (int e = 0; e < N_EXP; e++) if (e != i0 && p[e] > p[i1]) i1 = e;

        int pos0 = atomicAdd(&d_counts[i0], 1);
        d_tok [i0][pos0] = gwarp;
        d_gate[i0][pos0] = p[i0];
        int pos1 = atomicAdd(&d_counts[i1], 1);
        d_tok [i1][pos1] = gwarp;
        d_gate[i1][pos1] = p[i1];
    }
}

// ---------------- kernel 4: HMMA grouped GEMM -------------------
// Issue cp.async for one k-tile (Ah, Al, Bh, Bl subtiles), swizzled.
__device__ __forceinline__ void issue_tile(uint32_t smem_u, int buf, int kt,
                                           const int* tok_s,
                                           const __nv_bfloat16* whb,
                                           const __nv_bfloat16* wlb,
                                           int n0, int tid) {
    const uint32_t base = smem_u + SM_TILES + buf * BUF_BYTES;
    const int kk = kt * KT;
#pragma unroll
    for (int it = 0; it < 4; it++) {
        const int idx = tid + it * NTHREADS;   // 0..1023
        const int row = idx >> 3;              // 0..127
        const int chunk = idx & 7;             // 16B chunk in 128B row
        const uint32_t sw = (uint32_t)(row * 128 + ((chunk * 16) ^ ((row & 7) << 4)));
        const int t = tok_s[row];
        const size_t xo = (size_t)(t < 0 ? 0 : t) * H_DIM + kk + chunk * 8;
        const uint32_t ok = (t >= 0) ? 16u : 0u;
        cp_async16(base + sw, d_xh + xo, ok);
        cp_async16(base + TILE_BYTES + sw, d_xl + xo, ok);
        const size_t wo = (size_t)(n0 + row) * H_DIM + kk + chunk * 8;
        cp_async16(base + 2 * TILE_BYTES + sw, whb + wo, 16u);
        cp_async16(base + 3 * TILE_BYTES + sw, wlb + wo, 16u);
    }
}

__global__ void __launch_bounds__(NTHREADS, 1)
moe_gemm_mma(const float* __restrict__ eb, float* __restrict__ out) {
    extern __shared__ __align__(1024) char smem[];
    const int e   = blockIdx.z;
    const int cnt = d_counts[e];
    const int m0  = blockIdx.y * BM;
    if (m0 >= cnt) return;
    const int n0  = blockIdx.x * BN;
    const int tid = threadIdx.x;
    const uint32_t smem_u = smem_to_u32(smem);

    int*   tok_s = (int*)(smem + SM_TOK);
    float* gw_s  = (float*)(smem + SM_GATE);
    if (tid < BM) {
        int m = m0 + tid;
        tok_s[tid] = (m < cnt) ? d_tok [e][m] : -1;
        gw_s [tid] = (m < cnt) ? d_gate[e][m] : 0.f;
    }
    __syncthreads();

    const __nv_bfloat16* whb = d_wh + (size_t)e * H_DIM * H_DIM;
    const __nv_bfloat16* wlb = d_wl + (size_t)e * H_DIM * H_DIM;

    // warp mapping: 4 warps in m, 2 in n
    const int lane = tid & 31;
    const int wm = (tid >> 5) & 3;        // m warp: 32 rows
    const int wn = (tid >> 5) >> 2;       // n warp: 64 cols

    // ldmatrix per-lane address components
    const int ar   = lane & 15;                              // A matrix row within 16
    const int ak   = (lane >> 4) * 16;                       // A k-byte half select
    const int xora = (ar & 7) << 4;
    const int br   = (lane & 7) + ((lane >> 4) << 3);        // B n-row within 16
    const int bk   = ((lane >> 3) & 1) * 16;                 // B k-byte half select
    const int xorb = (br & 7) << 4;

    uint32_t aoff[2], boff[4];
#pragma unroll
    for (int mt = 0; mt < 2; mt++)
        aoff[mt] = (uint32_t)((wm * 32 + mt * 16 + ar) * 128);
#pragma unroll
    for (int nt2 = 0; nt2 < 4; nt2++)
        boff[nt2] = (uint32_t)((wn * 64 + nt2 * 16 + br) * 128);

    float acc[2][8][4];
#pragma unroll
    for (int i = 0; i < 2; i++)
#pragma unroll
        for (int j = 0; j < 8; j++)
#pragma unroll
            for (int q = 0; q < 4; q++) acc[i][j][q] = 0.f;

    // prologue
    issue_tile(smem_u, 0, 0, tok_s, whb, wlb, n0, tid);
    cp_commit();

    for (int kt = 0; kt < NKT; kt++) {
        const int cur = kt & 1;
        if (kt + 1 < NKT) {
            issue_tile(smem_u, cur ^ 1, kt + 1, tok_s, whb, wlb, n0, tid);
            cp_commit();
            cp_wait1();
        } else {
            cp_wait0();
        }
        __syncthreads();

        const uint32_t abase = smem_u + SM_TILES + cur * BUF_BYTES;
        const uint32_t bbase = abase + 2 * TILE_BYTES;
#pragma unroll
        for (int kkq = 0; kkq < KT / 16; kkq++) {   // 4 k16 steps
            const uint32_t akb = (uint32_t)((kkq * 32 + ak) ^ xora);
            const uint32_t bkb = (uint32_t)((kkq * 32 + bk) ^ xorb);
            uint32_t ah[2][4], al[2][4], bh[4][4], bl[4][4];
#pragma unroll
            for (int mt = 0; mt < 2; mt++) {
                ldsm_x4(ah[mt], abase + aoff[mt] + akb);
                ldsm_x4(al[mt], abase + TILE_BYTES + aoff[mt] + akb);
            }
#pragma unroll
            for (int nt2 = 0; nt2 < 4; nt2++) {
                ldsm_x4(bh[nt2], bbase + boff[nt2] + bkb);
                ldsm_x4(bl[nt2], bbase + TILE_BYTES + boff[nt2] + bkb);
            }
#pragma unroll
            for (int mt = 0; mt < 2; mt++)
#pragma unroll
                for (int nt2 = 0; nt2 < 4; nt2++) {
                    mma_bf16(acc[mt][2 * nt2 + 0], ah[mt], &bh[nt2][0]);
                    mma_bf16(acc[mt][2 * nt2 + 1], ah[mt], &bh[nt2][2]);
                    mma_bf16(acc[mt][2 * nt2 + 0], ah[mt], &bl[nt2][0]);
                    mma_bf16(acc[mt][2 * nt2 + 1], ah[mt], &bl[nt2][2]);
                    mma_bf16(acc[mt][2 * nt2 + 0], al[mt], &bh[nt2][0]);
                    mma_bf16(acc[mt][2 * nt2 + 1], al[mt], &bh[nt2][2]);
                }
        }
        __syncthreads();
    }

    // epilogue: y = gate * (acc + bias), atomic scatter per token row
#pragma unroll
    for (int mt = 0; mt < 2; mt++) {
        const int r0 = wm * 32 + mt * 16 + (lane >> 2);
        const int r1 = r0 + 8;
        const int t0 = tok_s[r0];
        const int t1 = tok_s[r1];
        const float g0 = gw_s[r0];
        const float g1 = gw_s[r1];
#pragma unroll
        for (int nt = 0; nt < 8; nt++) {
            const int col = n0 + wn * 64 + nt * 8 + 2 * (lane & 3);
            const float b0 = eb[e * H_DIM + col];
            const float b1 = eb[e * H_DIM + col + 1];
            if (t0 >= 0) {
                float* o = out + (size_t)t0 * H_DIM + col;
                atomicAdd(&o[0], g0 * (acc[mt][nt][0] + b0));
                atomicAdd(&o[1], g0 * (acc[mt][nt][1] + b1));
            }
            if (t1 >= 0) {
                float* o = out + (size_t)t1 * H_DIM + col;
                atomicAdd(&o[0], g1 * (acc[mt][nt][2] + b0));
                atomicAdd(&o[1], g1 * (acc[mt][nt][3] + b1));
            }
        }
    }
}

// ------------------------- launcher ------------------------------
extern "C" void kernel_launch(void* const* d_in, const int* in_sizes, int n_in,
                              void* d_out, int out_size) {
    const float* x   = (const float*)d_in[0];  // [4,2048,1024]
    const float* gw  = (const float*)d_in[1];  // [8,1024]
    const float* gb  = (const float*)d_in[2];  // [8]
    const float* ew  = (const float*)d_in[3];  // [8,1024,1024]
    const float* eb  = (const float*)d_in[4];  // [8,1024]
    float* out = (float*)d_out;

    cudaFuncSetAttribute(moe_gemm_mma,
                         cudaFuncAttributeMaxDynamicSharedMemorySize, SMEM_TOTAL);

    // 1) zero output + counters
    {
        int n4 = N_TOK * H_DIM / 4;
        moe_zero_kernel<<<(n4 + 255) / 256, 256>>>((float4*)out);
    }
    // 2) hi/lo bf16 split of x and w
    {
        int n4x = N_TOK * H_DIM / 4;
        int n4w = N_EXP * H_DIM * H_DIM / 4;
        moe_convert_kernel<<<(n4x + 255) / 256, 256>>>((const float4*)x, 0, n4x);
        moe_convert_kernel<<<(n4w + 255) / 256, 256>>>((const float4*)ew, 1, n4w);
    }
    // 3) gate + assignment (one warp/token)
    moe_gate_kernel<<<N_TOK / 8, 8 * 32>>>(x, gw, gb);
    // 4) HMMA grouped GEMM (128x128 tiles, bf16 hi/lo 3-term)
    {
        dim3 grid(H_DIM / BN, N_TOK / BM, N_EXP);  // (8, 64, 8)
        moe_gemm_mma<<<grid, NTHREADS, SMEM_TOTAL>>>(eb, out);
    }
}

// round 7
// speedup vs baseline: 6.8359x; 1.4975x over previous
#include <cuda_runtime.h>
#include <cuda_fp16.h>
#include <cstdint>

// Problem constants
#define H_DIM 1024
#define N_EXP 8
#define N_TOK 8192      // B*S
#define BM 128
#define BN 128
#define KT 64                 // k-elements per smem tile (fp16): 128B rows
#define NKT (H_DIM / KT)      // 16
#define NTHREADS 256

// SMEM layout (dynamic)
#define SM_TOK    0                       // 128 ints
#define SM_GATE   512                     // 128 floats
#define SM_TILES  1024
#define TILE_BYTES 16384                  // 128 rows x 128B
#define BUF_BYTES (3 * TILE_BYTES)        // Ah, Al, Wh
#define SMEM_TOTAL (SM_TILES + 2 * BUF_BYTES)   // 99328

// -------- scratch (allocation-free: __device__ globals) --------
__device__ int   d_counts[N_EXP];
__device__ int   d_tok [N_EXP][N_TOK];
__device__ float d_gate[N_EXP][N_TOK];
__device__ __half d_xh[(size_t)N_TOK * H_DIM];
__device__ __half d_xl[(size_t)N_TOK * H_DIM];
__device__ __half d_wh[(size_t)N_EXP * H_DIM * H_DIM];

// ---------------- PTX helpers (baseline sm_80+ features only) ----
__device__ __forceinline__ uint32_t smem_to_u32(const void* p) {
    uint32_t a;
    asm("{ .reg .u64 t; cvta.to.shared.u64 t, %1; cvt.u32.u64 %0, t; }"
        : "=r"(a) : "l"(p));
    return a;
}
__device__ __forceinline__ void cp_async16(uint32_t dst, const void* src, uint32_t src_size) {
    asm volatile("cp.async.cg.shared.global [%0], [%1], 16, %2;"
                 :: "r"(dst), "l"(src), "r"(src_size) : "memory");
}
__device__ __forceinline__ void cp_commit() {
    asm volatile("cp.async.commit_group;" ::: "memory");
}
__device__ __forceinline__ void cp_wait1() {
    asm volatile("cp.async.wait_group 1;" ::: "memory");
}
__device__ __forceinline__ void cp_wait0() {
    asm volatile("cp.async.wait_group 0;" ::: "memory");
}
__device__ __forceinline__ void ldsm_x4(uint32_t* r, uint32_t addr) {
    asm volatile("ldmatrix.sync.aligned.m8n8.x4.shared.b16 {%0,%1,%2,%3}, [%4];"
                 : "=r"(r[0]), "=r"(r[1]), "=r"(r[2]), "=r"(r[3]) : "r"(addr));
}
__device__ __forceinline__ void mma_fp16(float* d, const uint32_t* a, const uint32_t* b) {
    asm volatile("mma.sync.aligned.m16n8k16.row.col.f32.f16.f16.f32 "
                 "{%0,%1,%2,%3}, {%4,%5,%6,%7}, {%8,%9}, {%0,%1,%2,%3};"
                 : "+f"(d[0]), "+f"(d[1]), "+f"(d[2]), "+f"(d[3])
                 : "r"(a[0]), "r"(a[1]), "r"(a[2]), "r"(a[3]),
                   "r"(b[0]), "r"(b[1]));
}

// ---------------- kernel 1: zero out + counters ----------------
__global__ void moe_zero_kernel(float4* __restrict__ out4) {
    if (blockIdx.x == 0 && threadIdx.x < N_EXP) d_counts[threadIdx.x] = 0;
    size_t idx = (size_t)blockIdx.x * blockDim.x + threadIdx.x;
    if (idx < (size_t)N_TOK * H_DIM / 4)
        out4[idx] = make_float4(0.f, 0.f, 0.f, 0.f);
}

// ---------------- kernel 2: w -> fp16 (hi only) -----------------
__global__ void moe_convert_w(const float4* __restrict__ src, int n4) {
    int i = blockIdx.x * blockDim.x + threadIdx.x;
    if (i >= n4) return;
    float4 v = src[i];
    __half2* hi = (__half2*)d_wh;
    hi[i * 2 + 0] = __floats2half2_rn(v.x, v.y);
    hi[i * 2 + 1] = __floats2half2_rn(v.z, v.w);
}

// ---------------- kernel 3: fused gate + x hi/lo split ----------
// one warp per token: converts x row to fp16 hi/lo AND computes gate top-2
__global__ void moe_gate_kernel(const float* __restrict__ x,
                                const float* __restrict__ gw,
                                const float* __restrict__ gb) {
    int tok  = (blockIdx.x * blockDim.x + threadIdx.x) >> 5;
    int lane = threadIdx.x & 31;
    if (tok >= N_TOK) return;

    const float4* xr4 = (const float4*)(x + (size_t)tok * H_DIM);
    const float4* gw4 = (const float4*)gw;
    __half2* xh2 = (__half2*)(d_xh + (size_t)tok * H_DIM);
    __half2* xl2 = (__half2*)(d_xl + (size_t)tok * H_DIM);

    float acc[N_EXP];
#pragma unroll
    for (int e = 0; e < N_EXP; e++) acc[e] = 0.f;

    for (int h4 = lane; h4 < H_DIM / 4; h4 += 32) {
        float4 v = xr4[h4];
        // fp16 hi/lo split of x
        __half hx = __float2half_rn(v.x), hy = __float2half_rn(v.y);
        __half hz = __float2half_rn(v.z), hw = __float2half_rn(v.w);
        xh2[h4 * 2 + 0] = __halves2half2(hx, hy);
        xh2[h4 * 2 + 1] = __halves2half2(hz, hw);
        xl2[h4 * 2 + 0] = __floats2half2_rn(v.x - __half2float(hx), v.y - __half2float(hy));
        xl2[h4 * 2 + 1] = __floats2half2_rn(v.z - __half2float(hz), v.w - __half2float(hw));
        // gate accumulation
#pragma unroll
        for (int e = 0; e < N_EXP; e++) {
            float4 g = gw4[e * (H_DIM / 4) + h4];
            acc[e] += v.x * g.x + v.y * g.y + v.z * g.z + v.w * g.w;
        }
    }
#pragma unroll
    for (int e = 0; e < N_EXP; e++) {
#pragma unroll
        for (int off = 16; off; off >>= 1)
            acc[e] += __shfl_xor_sync(0xffffffffu, acc[e], off);
    }
    if (lane == 0) {
        float logit[N_EXP], mx = -1e30f;
#pragma unroll
        for (int e = 0; e < N_EXP; e++) { logit[e] = acc[e] + gb[e]; mx = fmaxf(mx, logit[e]); }
        float p[N_EXP], s = 0.f;
#pragma unroll
        for (int e = 0; e < N_EXP; e++) { p[e] = __expf(logit[e] - mx); s += p[e]; }
        float inv = 1.f / s;
#pragma unroll
        for (int e = 0; e < N_EXP; e++) p[e] *= inv;
        int i0 = 0;
#pragma unroll
        for (int e = 1; e < N_EXP; e++) if (p[e] > p[i0]) i0 = e;
        int i1 = (i0 == 0) ? 1 : 0;
#pragma unroll
        for (int e = 0; e < N_EXP; e++) if (e != i0 && p[e] > p[i1]) i1 = e;

        int pos0 = atomicAdd(&d_counts[i0], 1);
        d_tok [i0][pos0] = tok;
        d_gate[i0][pos0] = p[i0];
        int pos1 = atomicAdd(&d_counts[i1], 1);
        d_tok [i1][pos1] = tok;
        d_gate[i1][pos1] = p[i1];
    }
}

// ---------------- kernel 4: HMMA grouped GEMM (fp16 2-term) -----
__device__ __forceinline__ void issue_tile(uint32_t smem_u, int buf, int kt,
                                           const int* tok_s,
                                           const __half* whb,
                                           int n0, int tid) {
    const uint32_t base = smem_u + SM_TILES + buf * BUF_BYTES;
    const int kk = kt * KT;
#pragma unroll
    for (int it = 0; it < 4; it++) {
        const int idx = tid + it * NTHREADS;   // 0..1023
        const int row = idx >> 3;              // 0..127
        const int chunk = idx & 7;             // 16B chunk in 128B row
        const uint32_t sw = (uint32_t)(row * 128 + ((chunk * 16) ^ ((row & 7) << 4)));
        const int t = tok_s[row];
        const size_t xo = (size_t)(t < 0 ? 0 : t) * H_DIM + kk + chunk * 8;
        const uint32_t ok = (t >= 0) ? 16u : 0u;
        cp_async16(base + sw, d_xh + xo, ok);
        cp_async16(base + TILE_BYTES + sw, d_xl + xo, ok);
        const size_t wo = (size_t)(n0 + row) * H_DIM + kk + chunk * 8;
        cp_async16(base + 2 * TILE_BYTES + sw, whb + wo, 16u);
    }
}

__global__ void __launch_bounds__(NTHREADS, 2)
moe_gemm_mma(const float* __restrict__ eb, float* __restrict__ out) {
    extern __shared__ __align__(1024) char smem[];
    const int e   = blockIdx.z;
    const int cnt = d_counts[e];
    const int m0  = blockIdx.y * BM;
    if (m0 >= cnt) return;
    const int n0  = blockIdx.x * BN;
    const int tid = threadIdx.x;
    const uint32_t smem_u = smem_to_u32(smem);

    int*   tok_s = (int*)(smem + SM_TOK);
    float* gw_s  = (float*)(smem + SM_GATE);
    if (tid < BM) {
        int m = m0 + tid;
        tok_s[tid] = (m < cnt) ? d_tok [e][m] : -1;
        gw_s [tid] = (m < cnt) ? d_gate[e][m] : 0.f;
    }
    __syncthreads();

    const __half* whb = d_wh + (size_t)e * H_DIM * H_DIM;

    // warp mapping: 4 warps in m, 2 in n
    const int lane = tid & 31;
    const int wm = (tid >> 5) & 3;        // m warp: 32 rows
    const int wn = (tid >> 5) >> 2;       // n warp: 64 cols

    const int ar   = lane & 15;
    const int ak   = (lane >> 4) * 16;
    const int xora = (ar & 7) << 4;
    const int br   = (lane & 7) + ((lane >> 4) << 3);
    const int bk   = ((lane >> 3) & 1) * 16;
    const int xorb = (br & 7) << 4;

    uint32_t aoff[2], boff[4];
#pragma unroll
    for (int mt = 0; mt < 2; mt++)
        aoff[mt] = (uint32_t)((wm * 32 + mt * 16 + ar) * 128);
#pragma unroll
    for (int nt2 = 0; nt2 < 4; nt2++)
        boff[nt2] = (uint32_t)((wn * 64 + nt2 * 16 + br) * 128);

    float acc[2][8][4];
#pragma unroll
    for (int i = 0; i < 2; i++)
#pragma unroll
        for (int j = 0; j < 8; j++)
#pragma unroll
            for (int q = 0; q < 4; q++) acc[i][j][q] = 0.f;

    // prologue
    issue_tile(smem_u, 0, 0, tok_s, whb, n0, tid);
    cp_commit();

    for (int kt = 0; kt < NKT; kt++) {
        const int cur = kt & 1;
        if (kt + 1 < NKT) {
            issue_tile(smem_u, cur ^ 1, kt + 1, tok_s, whb, n0, tid);
            cp_commit();
            cp_wait1();
        } else {
            cp_wait0();
        }
        __syncthreads();

        const uint32_t abase = smem_u + SM_TILES + cur * BUF_BYTES;
        const uint32_t bbase = abase + 2 * TILE_BYTES;
#pragma unroll
        for (int kkq = 0; kkq < KT / 16; kkq++) {   // 4 k16 steps
            const uint32_t akb = (uint32_t)((kkq * 32 + ak) ^ xora);
            const uint32_t bkb = (uint32_t)((kkq * 32 + bk) ^ xorb);
            uint32_t ah[2][4], al[2][4], bh[4][4];
#pragma unroll
            for (int mt = 0; mt < 2; mt++) {
                ldsm_x4(ah[mt], abase + aoff[mt] + akb);
                ldsm_x4(al[mt], abase + TILE_BYTES + aoff[mt] + akb);
            }
#pragma unroll
            for (int nt2 = 0; nt2 < 4; nt2++)
                ldsm_x4(bh[nt2], bbase + boff[nt2] + bkb);
#pragma unroll
            for (int mt = 0; mt < 2; mt++)
#pragma unroll
                for (int nt2 = 0; nt2 < 4; nt2++) {
                    mma_fp16(acc[mt][2 * nt2 + 0], ah[mt], &bh[nt2][0]);
                    mma_fp16(acc[mt][2 * nt2 + 1], ah[mt], &bh[nt2][2]);
                    mma_fp16(acc[mt][2 * nt2 + 0], al[mt], &bh[nt2][0]);
                    mma_fp16(acc[mt][2 * nt2 + 1], al[mt], &bh[nt2][2]);
                }
        }
        __syncthreads();
    }

    // epilogue: y = gate * (acc + bias), atomic scatter per token row
#pragma unroll
    for (int mt = 0; mt < 2; mt++) {
        const int r0 = wm * 32 + mt * 16 + (lane >> 2);
        const int r1 = r0 + 8;
        const int t0 = tok_s[r0];
        const int t1 = tok_s[r1];
        const float g0 = gw_s[r0];
        const float g1 = gw_s[r1];
#pragma unroll
        for (int nt = 0; nt < 8; nt++) {
            const int col = n0 + wn * 64 + nt * 8 + 2 * (lane & 3);
            const float b0 = eb[e * H_DIM + col];
            const float b1 = eb[e * H_DIM + col + 1];
            if (t0 >= 0) {
                float* o = out + (size_t)t0 * H_DIM + col;
                atomicAdd(&o[0], g0 * (acc[mt][nt][0] + b0));
                atomicAdd(&o[1], g0 * (acc[mt][nt][1] + b1));
            }
            if (t1 >= 0) {
                float* o = out + (size_t)t1 * H_DIM + col;
                atomicAdd(&o[0], g1 * (acc[mt][nt][2] + b0));
                atomicAdd(&o[1], g1 * (acc[mt][nt][3] + b1));
            }
        }
    }
}

// ------------------------- launcher ------------------------------
extern "C" void kernel_launch(void* const* d_in, const int* in_sizes, int n_in,
                              void* d_out, int out_size) {
    const float* x   = (const float*)d_in[0];  // [4,2048,1024]
    const float* gw  = (const float*)d_in[1];  // [8,1024]
    const float* gb  = (const float*)d_in[2];  // [8]
    const float* ew  = (const float*)d_in[3];  // [8,1024,1024]
    const float* eb  = (const float*)d_in[4];  // [8,1024]
    float* out = (float*)d_out;

    cudaFuncSetAttribute(moe_gemm_mma,
                         cudaFuncAttributeMaxDynamicSharedMemorySize, SMEM_TOTAL);

    // 1) zero output + counters
    {
        int n4 = N_TOK * H_DIM / 4;
        moe_zero_kernel<<<(n4 + 255) / 256, 256>>>((float4*)out);
    }
    // 2) w -> fp16
    {
        int n4w = N_EXP * H_DIM * H_DIM / 4;
        moe_convert_w<<<(n4w + 255) / 256, 256>>>((const float4*)ew, n4w);
    }
    // 3) fused gate + x split (one warp/token)
    moe_gate_kernel<<<N_TOK / 8, 8 * 32>>>(x, gw, gb);
    // 4) HMMA grouped GEMM (128x128 tiles, fp16 2-term)
    {
        dim3 grid(H_DIM / BN, N_TOK / BM, N_EXP);  // (8, 64, 8)
        moe_gemm_mma<<<grid, NTHREADS, SMEM_TOTAL>>>(eb, out);
    }
}

// round 8
// speedup vs baseline: 9.7503x; 1.4263x over previous
#include <cuda_runtime.h>
#include <cuda_fp16.h>
#include <cstdint>

// Problem constants
#define H_DIM 1024
#define N_EXP 8
#define N_TOK 8192      // B*S
#define BM 128
#define BN 128
#define KT 64                 // k-elements per smem tile (fp16): 128B rows
#define NKT (H_DIM / KT)      // 16
#define NTHREADS 256

// SMEM layout (dynamic)
#define SM_TOK    0                       // 128 ints
#define SM_GATE   512                     // 128 floats
#define SM_TILES  1024
#define TILE_BYTES 16384                  // 128 rows x 128B
#define BUF_BYTES (2 * TILE_BYTES)        // Ah, Wh
#define SMEM_TOTAL (SM_TILES + 2 * BUF_BYTES)   // 66560

// -------- scratch (allocation-free: __device__ globals) --------
__device__ int   d_counts[N_EXP];
__device__ int   d_tok [N_EXP][N_TOK];
__device__ float d_gate[N_EXP][N_TOK];
__device__ __half d_xh[(size_t)N_TOK * H_DIM];
__device__ __half d_wh[(size_t)N_EXP * H_DIM * H_DIM];

// ---------------- PTX helpers (baseline sm_80+ features only) ----
__device__ __forceinline__ uint32_t smem_to_u32(const void* p) {
    uint32_t a;
    asm("{ .reg .u64 t; cvta.to.shared.u64 t, %1; cvt.u32.u64 %0, t; }"
        : "=r"(a) : "l"(p));
    return a;
}
__device__ __forceinline__ void cp_async16(uint32_t dst, const void* src, uint32_t src_size) {
    asm volatile("cp.async.cg.shared.global [%0], [%1], 16, %2;"
                 :: "r"(dst), "l"(src), "r"(src_size) : "memory");
}
__device__ __forceinline__ void cp_commit() {
    asm volatile("cp.async.commit_group;" ::: "memory");
}
__device__ __forceinline__ void cp_wait1() {
    asm volatile("cp.async.wait_group 1;" ::: "memory");
}
__device__ __forceinline__ void cp_wait0() {
    asm volatile("cp.async.wait_group 0;" ::: "memory");
}
__device__ __forceinline__ void ldsm_x4(uint32_t* r, uint32_t addr) {
    asm volatile("ldmatrix.sync.aligned.m8n8.x4.shared.b16 {%0,%1,%2,%3}, [%4];"
                 : "=r"(r[0]), "=r"(r[1]), "=r"(r[2]), "=r"(r[3]) : "r"(addr));
}
__device__ __forceinline__ void mma_fp16(float* d, const uint32_t* a, const uint32_t* b) {
    asm volatile("mma.sync.aligned.m16n8k16.row.col.f32.f16.f16.f32 "
                 "{%0,%1,%2,%3}, {%4,%5,%6,%7}, {%8,%9}, {%0,%1,%2,%3};"
                 : "+f"(d[0]), "+f"(d[1]), "+f"(d[2]), "+f"(d[3])
                 : "r"(a[0]), "r"(a[1]), "r"(a[2]), "r"(a[3]),
                   "r"(b[0]), "r"(b[1]));
}

// ---------------- kernel 1: zero out + counters ----------------
__global__ void moe_zero_kernel(float4* __restrict__ out4) {
    if (blockIdx.x == 0 && threadIdx.x < N_EXP) d_counts[threadIdx.x] = 0;
    size_t idx = (size_t)blockIdx.x * blockDim.x + threadIdx.x;
    if (idx < (size_t)N_TOK * H_DIM / 4)
        out4[idx] = make_float4(0.f, 0.f, 0.f, 0.f);
}

// ---------------- kernel 2: w -> fp16 ---------------------------
__global__ void moe_convert_w(const float4* __restrict__ src, int n4) {
    int i = blockIdx.x * blockDim.x + threadIdx.x;
    if (i >= n4) return;
    float4 v = src[i];
    __half2* hi = (__half2*)d_wh;
    hi[i * 2 + 0] = __floats2half2_rn(v.x, v.y);
    hi[i * 2 + 1] = __floats2half2_rn(v.z, v.w);
}

// ---------------- kernel 3: fused gate + x -> fp16 --------------
// one warp per token: converts x row to fp16 AND computes gate top-2
__global__ void moe_gate_kernel(const float* __restrict__ x,
                                const float* __restrict__ gw,
                                const float* __restrict__ gb) {
    int tok  = (blockIdx.x * blockDim.x + threadIdx.x) >> 5;
    int lane = threadIdx.x & 31;
    if (tok >= N_TOK) return;

    const float4* xr4 = (const float4*)(x + (size_t)tok * H_DIM);
    const float4* gw4 = (const float4*)gw;
    __half2* xh2 = (__half2*)(d_xh + (size_t)tok * H_DIM);

    float acc[N_EXP];
#pragma unroll
    for (int e = 0; e < N_EXP; e++) acc[e] = 0.f;

    for (int h4 = lane; h4 < H_DIM / 4; h4 += 32) {
        float4 v = xr4[h4];
        xh2[h4 * 2 + 0] = __floats2half2_rn(v.x, v.y);
        xh2[h4 * 2 + 1] = __floats2half2_rn(v.z, v.w);
#pragma unroll
        for (int e = 0; e < N_EXP; e++) {
            float4 g = gw4[e * (H_DIM / 4) + h4];
            acc[e] += v.x * g.x + v.y * g.y + v.z * g.z + v.w * g.w;
        }
    }
#pragma unroll
    for (int e = 0; e < N_EXP; e++) {
#pragma unroll
        for (int off = 16; off; off >>= 1)
            acc[e] += __shfl_xor_sync(0xffffffffu, acc[e], off);
    }
    if (lane == 0) {
        float logit[N_EXP], mx = -1e30f;
#pragma unroll
        for (int e = 0; e < N_EXP; e++) { logit[e] = acc[e] + gb[e]; mx = fmaxf(mx, logit[e]); }
        float p[N_EXP], s = 0.f;
#pragma unroll
        for (int e = 0; e < N_EXP; e++) { p[e] = __expf(logit[e] - mx); s += p[e]; }
        float inv = 1.f / s;
#pragma unroll
        for (int e = 0; e < N_EXP; e++) p[e] *= inv;
        int i0 = 0;
#pragma unroll
        for (int e = 1; e < N_EXP; e++) if (p[e] > p[i0]) i0 = e;
        int i1 = (i0 == 0) ? 1 : 0;
#pragma unroll
        for (int e = 0; e < N_EXP; e++) if (e != i0 && p[e] > p[i1]) i1 = e;

        int pos0 = atomicAdd(&d_counts[i0], 1);
        d_tok [i0][pos0] = tok;
        d_gate[i0][pos0] = p[i0];
        int pos1 = atomicAdd(&d_counts[i1], 1);
        d_tok [i1][pos1] = tok;
        d_gate[i1][pos1] = p[i1];
    }
}

// ---------------- kernel 4: HMMA grouped GEMM (fp16 1-term) -----
__device__ __forceinline__ void issue_tile(uint32_t smem_u, int buf, int kt,
                                           const int* tok_s,
                                           const __half* whb,
                                           int n0, int tid) {
    const uint32_t base = smem_u + SM_TILES + buf * BUF_BYTES;
    const int kk = kt * KT;
#pragma unroll
    for (int it = 0; it < 4; it++) {
        const int idx = tid + it * NTHREADS;   // 0..1023
        const int row = idx >> 3;              // 0..127
        const int chunk = idx & 7;             // 16B chunk in 128B row
        const uint32_t sw = (uint32_t)(row * 128 + ((chunk * 16) ^ ((row & 7) << 4)));
        const int t = tok_s[row];
        const size_t xo = (size_t)(t < 0 ? 0 : t) * H_DIM + kk + chunk * 8;
        const uint32_t ok = (t >= 0) ? 16u : 0u;
        cp_async16(base + sw, d_xh + xo, ok);
        const size_t wo = (size_t)(n0 + row) * H_DIM + kk + chunk * 8;
        cp_async16(base + TILE_BYTES + sw, whb + wo, 16u);
    }
}

__global__ void __launch_bounds__(NTHREADS, 2)
moe_gemm_mma(const float* __restrict__ eb, float* __restrict__ out) {
    extern __shared__ __align__(1024) char smem[];
    const int e   = blockIdx.z;
    const int cnt = d_counts[e];
    const int m0  = blockIdx.y * BM;
    if (m0 >= cnt) return;
    const int n0  = blockIdx.x * BN;
    const int tid = threadIdx.x;
    const uint32_t smem_u = smem_to_u32(smem);

    int*   tok_s = (int*)(smem + SM_TOK);
    float* gw_s  = (float*)(smem + SM_GATE);
    if (tid < BM) {
        int m = m0 + tid;
        tok_s[tid] = (m < cnt) ? d_tok [e][m] : -1;
        gw_s [tid] = (m < cnt) ? d_gate[e][m] : 0.f;
    }
    __syncthreads();

    const __half* whb = d_wh + (size_t)e * H_DIM * H_DIM;

    // warp mapping: 4 warps in m, 2 in n
    const int lane = tid & 31;
    const int wm = (tid >> 5) & 3;        // m warp: 32 rows
    const int wn = (tid >> 5) >> 2;       // n warp: 64 cols

    const int ar   = lane & 15;
    const int ak   = (lane >> 4) * 16;
    const int xora = (ar & 7) << 4;
    const int br   = (lane & 7) + ((lane >> 4) << 3);
    const int bk   = ((lane >> 3) & 1) * 16;
    const int xorb = (br & 7) << 4;

    uint32_t aoff[2], boff[4];
#pragma unroll
    for (int mt = 0; mt < 2; mt++)
        aoff[mt] = (uint32_t)((wm * 32 + mt * 16 + ar) * 128);
#pragma unroll
    for (int nt2 = 0; nt2 < 4; nt2++)
        boff[nt2] = (uint32_t)((wn * 64 + nt2 * 16 + br) * 128);

    float acc[2][8][4];
#pragma unroll
    for (int i = 0; i < 2; i++)
#pragma unroll
        for (int j = 0; j < 8; j++)
#pragma unroll
            for (int q = 0; q < 4; q++) acc[i][j][q] = 0.f;

    // prologue
    issue_tile(smem_u, 0, 0, tok_s, whb, n0, tid);
    cp_commit();

    for (int kt = 0; kt < NKT; kt++) {
        const int cur = kt & 1;
        if (kt + 1 < NKT) {
            issue_tile(smem_u, cur ^ 1, kt + 1, tok_s, whb, n0, tid);
            cp_commit();
            cp_wait1();
        } else {
            cp_wait0();
        }
        __syncthreads();

        const uint32_t abase = smem_u + SM_TILES + cur * BUF_BYTES;
        const uint32_t bbase = abase + TILE_BYTES;
#pragma unroll
        for (int kkq = 0; kkq < KT / 16; kkq++) {   // 4 k16 steps
            const uint32_t akb = (uint32_t)((kkq * 32 + ak) ^ xora);
            const uint32_t bkb = (uint32_t)((kkq * 32 + bk) ^ xorb);
            uint32_t ah[2][4], bh[4][4];
#pragma unroll
            for (int mt = 0; mt < 2; mt++)
                ldsm_x4(ah[mt], abase + aoff[mt] + akb);
#pragma unroll
            for (int nt2 = 0; nt2 < 4; nt2++)
                ldsm_x4(bh[nt2], bbase + boff[nt2] + bkb);
#pragma unroll
            for (int mt = 0; mt < 2; mt++)
#pragma unroll
                for (int nt2 = 0; nt2 < 4; nt2++) {
                    mma_fp16(acc[mt][2 * nt2 + 0], ah[mt], &bh[nt2][0]);
                    mma_fp16(acc[mt][2 * nt2 + 1], ah[mt], &bh[nt2][2]);
                }
        }
        __syncthreads();
    }

    // epilogue: y = gate * (acc + bias), atomic scatter per token row
#pragma unroll
    for (int mt = 0; mt < 2; mt++) {
        const int r0 = wm * 32 + mt * 16 + (lane >> 2);
        const int r1 = r0 + 8;
        const int t0 = tok_s[r0];
        const int t1 = tok_s[r1];
        const float g0 = gw_s[r0];
        const float g1 = gw_s[r1];
#pragma unroll
        for (int nt = 0; nt < 8; nt++) {
            const int col = n0 + wn * 64 + nt * 8 + 2 * (lane & 3);
            const float b0 = eb[e * H_DIM + col];
            const float b1 = eb[e * H_DIM + col + 1];
            if (t0 >= 0) {
                float* o = out + (size_t)t0 * H_DIM + col;
                atomicAdd(&o[0], g0 * (acc[mt][nt][0] + b0));
                atomicAdd(&o[1], g0 * (acc[mt][nt][1] + b1));
            }
            if (t1 >= 0) {
                float* o = out + (size_t)t1 * H_DIM + col;
                atomicAdd(&o[0], g1 * (acc[mt][nt][2] + b0));
                atomicAdd(&o[1], g1 * (acc[mt][nt][3] + b1));
            }
        }
    }
}

// ------------------------- launcher ------------------------------
extern "C" void kernel_launch(void* const* d_in, const int* in_sizes, int n_in,
                              void* d_out, int out_size) {
    const float* x   = (const float*)d_in[0];  // [4,2048,1024]
    const float* gw  = (const float*)d_in[1];  // [8,1024]
    const float* gb  = (const float*)d_in[2];  // [8]
    const float* ew  = (const float*)d_in[3];  // [8,1024,1024]
    const float* eb  = (const float*)d_in[4];  // [8,1024]
    float* out = (float*)d_out;

    cudaFuncSetAttribute(moe_gemm_mma,
                         cudaFuncAttributeMaxDynamicSharedMemorySize, SMEM_TOTAL);

    // 1) zero output + counters
    {
        int n4 = N_TOK * H_DIM / 4;
        moe_zero_kernel<<<(n4 + 255) / 256, 256>>>((float4*)out);
    }
    // 2) w -> fp16
    {
        int n4w = N_EXP * H_DIM * H_DIM / 4;
        moe_convert_w<<<(n4w + 255) / 256, 256>>>((const float4*)ew, n4w);
    }
    // 3) fused gate + x fp16 convert (one warp/token)
    moe_gate_kernel<<<N_TOK / 8, 8 * 32>>>(x, gw, gb);
    // 4) HMMA grouped GEMM (128x128 tiles, fp16 single-term)
    {
        dim3 grid(H_DIM / BN, N_TOK / BM, N_EXP);  // (8, 64, 8)
        moe_gemm_mma<<<grid, NTHREADS, SMEM_TOTAL>>>(eb, out);
    }
}